// round 11
// baseline (speedup 1.0000x reference)
#include <cuda_runtime.h>
#include <cuda_bf16.h>
#include <cstdint>

#define BATCH 1024
#define VOCAB 50000
#define DIM   300

#define BM      64
#define BN      304             // 38 n8-tiles, covers DIM=300
#define BN_ALLOC 320            // allocation/prep padding
#define KC      32
#define SPLITS  9
#define SEG     5568            // SPLITS*SEG = 50112 >= VOCAB, mult of KC
#define K_PAD   50112
#define NCHUNK  (SEG / KC)      // 174

// -------- static device scratch (no allocations allowed) --------
// B stored PERMUTED: within each 16-element k-group, word w (k pair) sits at
// position perm8(w) = (w&3)*2 + (w>>2), so fragment pairs (w, w+4) are adjacent.
__device__ __nv_bfloat16 g_bhi[(size_t)BN_ALLOC * K_PAD];   // weight hi, [n][k-perm]
__device__ __nv_bfloat16 g_blo[(size_t)BN_ALLOC * K_PAD];   // weight lo, [n][k-perm]
__device__ float g_partial[(size_t)SPLITS * BATCH * DIM];

// smem layout. Row = 64B data + 32B pad -> 96B stride: LDS.64 frag loads are
// bank-conflict-free (lr*24 mod 32 = {0,24,16,8} tiles all banks per 16-lane phase).
#define A_STRIDE 96
#define A_BYTES  (64 * A_STRIDE)        // 6144
#define B_BYTES  (BN * A_STRIDE)        // 29184
#define BUF_BYTES (2 * A_BYTES + 2 * B_BYTES)   // 70656
#define A_HI(b) ((b) * BUF_BYTES + 0)
#define A_LO(b) ((b) * BUF_BYTES + A_BYTES)
#define B_HI(b) ((b) * BUF_BYTES + 2 * A_BYTES)
#define B_LO(b) ((b) * BUF_BYTES + 2 * A_BYTES + B_BYTES)
#define SMEM_TOTAL (2 * BUF_BYTES)      // 141312

__device__ __forceinline__ uint32_t smem_u32(const void* p) {
    uint32_t a;
    asm("{ .reg .u64 t; cvta.to.shared.u64 t, %1; cvt.u32.u64 %0, t; }"
        : "=r"(a) : "l"(p));
    return a;
}
__device__ __forceinline__ void cp_async16(uint32_t dst, const void* src) {
    asm volatile("{ .reg .u64 g; cvta.to.global.u64 g, %1; "
                 "cp.async.ca.shared.global [%0], [g], 16; }"
                 :: "r"(dst), "l"(src) : "memory");
}
#define CP_COMMIT() asm volatile("cp.async.commit_group;" ::: "memory")
#define CP_WAIT0()  asm volatile("cp.async.wait_group 0;" ::: "memory")

__device__ __forceinline__ void mma16816(float* d, const uint32_t* a,
                                         uint32_t b0, uint32_t b1) {
    asm volatile("mma.sync.aligned.m16n8k16.row.col.f32.bf16.bf16.f32 "
                 "{%0,%1,%2,%3}, {%4,%5,%6,%7}, {%8,%9}, {%0,%1,%2,%3};"
                 : "+f"(d[0]), "+f"(d[1]), "+f"(d[2]), "+f"(d[3])
                 : "r"(a[0]), "r"(a[1]), "r"(a[2]), "r"(a[3]), "r"(b0), "r"(b1));
}

// split (x,y) into packed bf16x2 hi + lo (low half = x)
__device__ __forceinline__ void cvt_split2(float x, float y, uint32_t& h, uint32_t& l) {
    uint32_t hh;
    asm("cvt.rn.bf16x2.f32 %0, %1, %2;" : "=r"(hh) : "f"(y), "f"(x));
    float hx = __uint_as_float(hh << 16);
    float hy = __uint_as_float(hh & 0xFFFF0000u);
    float lx = x - hx, ly = y - hy;
    asm("cvt.rn.bf16x2.f32 %0, %1, %2;" : "=r"(l) : "f"(ly), "f"(lx));
    h = hh;
}

__host__ __device__ __forceinline__ constexpr int perm8(int w) {
    return (w & 3) * 2 + (w >> 2);
}

// ---------------- prep: weight f32 [K][300] -> permuted bf16 hi/lo [320][K_PAD] --------
__global__ __launch_bounds__(256) void prep_kernel(const float* __restrict__ weight)
{
    __shared__ float t[64][33];
    const int k0 = blockIdx.x * 64;
    const int n0 = blockIdx.y * 32;
    const int tx = threadIdx.x & 31;
    const int ty = threadIdx.x >> 5;     // 0..7
#pragma unroll
    for (int i = 0; i < 8; i++) {
        const int k = k0 + ty + i * 8;
        const int n = n0 + tx;
        t[ty + i * 8][tx] = (k < VOCAB && n < DIM) ? weight[(size_t)k * DIM + n] : 0.f;
    }
    __syncthreads();
    const int nl = threadIdx.x >> 3;           // 0..31
    const int kg = (threadIdx.x & 7) * 8;      // 0..56 (8 consecutive k)
    const size_t rowoff = (size_t)(n0 + nl) * K_PAD + k0 + (kg & ~15);
#pragma unroll
    for (int jw = 0; jw < 4; jw++) {
        const float v0 = t[kg + 2 * jw][nl];
        const float v1 = t[kg + 2 * jw + 1][nl];
        uint32_t hw, lw;
        cvt_split2(v0, v1, hw, lw);
        const int pos = perm8(((kg >> 1) + jw) & 7);
        *reinterpret_cast<uint32_t*>(g_bhi + rowoff + 2 * pos) = hw;
        *reinterpret_cast<uint32_t*>(g_blo + rowoff + 2 * pos) = lw;
    }
}

// ---------------- GEMM: HMMA bf16 3-term split, split-K, permuted LDS.64 frags ---------
__global__ __launch_bounds__(256, 1) void gemm_kernel(const float* __restrict__ labels)
{
    extern __shared__ char smem[];
    const uint32_t smem_base = smem_u32(smem);

    const int tid = threadIdx.x;
    const int lane = tid & 31;
    const int wid = tid >> 5;
    const int lr = lane >> 2;            // 0..7
    const int lc = lane & 3;             // 0..3
    const int m_strip = wid & 3;         // 4 m16 strips
    const int nt0 = (wid >> 2) * 19;     // n-tile base: 0 or 19

    const int row0 = blockIdx.x * BM;
    const int s = blockIdx.y;
    const int k_start = s * SEG;

    // A f32 staging indices
    const int arow = tid >> 3;           // 0..31 (rows r and r+32)
    const int af4 = tid & 7;             // float4 phase (k = af4*4..af4*4+3)

    float acc[19][4];
#pragma unroll
    for (int nt = 0; nt < 19; nt++)
#pragma unroll
        for (int i = 0; i < 4; i++) acc[nt][i] = 0.f;

    auto loadA = [&](int kc0, float4* v) {
#pragma unroll
        for (int i = 0; i < 2; i++) {
            const int r = row0 + arow + i * 32;
            const int k = kc0 + af4 * 4;
            const float* src = labels + (size_t)r * VOCAB + k;
            if (k + 3 < VOCAB) {
                v[i] = *reinterpret_cast<const float4*>(src);
            } else {
                v[i].x = (k     < VOCAB) ? src[0] : 0.f;
                v[i].y = (k + 1 < VOCAB) ? src[1] : 0.f;
                v[i].z = (k + 2 < VOCAB) ? src[2] : 0.f;
                v[i].w = (k + 3 < VOCAB) ? src[3] : 0.f;
            }
        }
    };
    // writes A with the same permuted word order as B
    auto stsA = [&](int buf, const float4* v) {
        const int g = (af4 >> 2) * 32;                 // 16-k group byte base
        const int w0 = (2 * af4) & 7;
        const int p0 = perm8(w0) * 4;
        const int p1 = perm8(w0 + 1) * 4;
#pragma unroll
        for (int i = 0; i < 2; i++) {
            uint32_t h0, l0, h1, l1;
            cvt_split2(v[i].x, v[i].y, h0, l0);
            cvt_split2(v[i].z, v[i].w, h1, l1);
            const int off = (arow + i * 32) * A_STRIDE + g;
            *reinterpret_cast<uint32_t*>(smem + A_HI(buf) + off + p0) = h0;
            *reinterpret_cast<uint32_t*>(smem + A_HI(buf) + off + p1) = h1;
            *reinterpret_cast<uint32_t*>(smem + A_LO(buf) + off + p0) = l0;
            *reinterpret_cast<uint32_t*>(smem + A_LO(buf) + off + p1) = l1;
        }
    };
    auto loadB = [&](int kc0, int buf) {
#pragma unroll
        for (int i = 0; i < 5; i++) {
            const int idx = tid + 256 * i;     // valid < 1216
            if (idx < BN * 4) {
                const int n = idx >> 2;
                const int seg = idx & 3;
                const int doff = n * A_STRIDE + seg * 16;
                const size_t goff = (size_t)n * K_PAD + kc0 + seg * 8;
                cp_async16(smem_base + B_HI(buf) + doff, g_bhi + goff);
                cp_async16(smem_base + B_LO(buf) + doff, g_blo + goff);
            }
        }
        CP_COMMIT();
    };
    auto compute = [&](int buf) {
        const int abase = A_HI(buf) + (m_strip * 16 + lr) * A_STRIDE + lc * 8;
        const int bbase = B_HI(buf) + (nt0 * 8 + lr) * A_STRIDE + lc * 8;
        // A fragments via LDS.64: pair (a0,a2) adjacent under permutation
        uint32_t ah[2][4], al[2][4];
#pragma unroll
        for (int kk = 0; kk < 2; kk++) {
            const uint2 h0 = *reinterpret_cast<const uint2*>(smem + abase + kk * 32);
            const uint2 h1 = *reinterpret_cast<const uint2*>(smem + abase + 8 * A_STRIDE + kk * 32);
            ah[kk][0] = h0.x; ah[kk][1] = h1.x; ah[kk][2] = h0.y; ah[kk][3] = h1.y;
            const uint2 l0 = *reinterpret_cast<const uint2*>(smem + abase + A_BYTES + kk * 32);
            const uint2 l1 = *reinterpret_cast<const uint2*>(smem + abase + A_BYTES + 8 * A_STRIDE + kk * 32);
            al[kk][0] = l0.x; al[kk][1] = l1.x; al[kk][2] = l0.y; al[kk][3] = l1.y;
        }
        // term-outermost; B fragment = single LDS.64 (b0,b1 adjacent)
#pragma unroll
        for (int t = 0; t < 3; t++) {
            const int bregion = (t == 1) ? B_BYTES : 0;   // t==1 -> B lo
#pragma unroll
            for (int kk = 0; kk < 2; kk++) {
                const uint32_t* af_ = (t == 2) ? al[kk] : ah[kk];
#pragma unroll
                for (int nt = 0; nt < 19; nt++) {
                    const uint2 b = *reinterpret_cast<const uint2*>(
                        smem + bbase + bregion + nt * 8 * A_STRIDE + kk * 32);
                    mma16816(acc[nt], af_, b.x, b.y);
                }
            }
        }
    };

    // ---- prologue: stage chunk 0 ----
    {
        float4 v[2];
        loadB(k_start, 0);
        loadA(k_start, v);
        stsA(0, v);
        CP_WAIT0();
        __syncthreads();
    }

    // ---- main loop: issue loads early, hide LDG/cp.async under compute ----
    for (int c = 0; c < NCHUNK; c++) {
        const int buf = c & 1;
        const bool has_next = (c + 1 < NCHUNK);
        float4 v[2];
        if (has_next) {
            loadB(k_start + (c + 1) * KC, buf ^ 1);   // async into other buffer
            loadA(k_start + (c + 1) * KC, v);          // LDG in flight during compute
        }
        compute(buf);
        if (has_next) {
            stsA(buf ^ 1, v);                          // consume LDG after compute
            CP_WAIT0();
        }
        __syncthreads();
    }

    // ---- epilogue: write split-K partials ----
    float* outp = g_partial + (size_t)s * BATCH * DIM;
    const int r0 = row0 + m_strip * 16 + lr;
#pragma unroll
    for (int nt = 0; nt < 19; nt++) {
        const int col = (nt0 + nt) * 8 + 2 * lc;
        if (col < DIM) {
            outp[(size_t)r0 * DIM + col] = acc[nt][0];
            if (col + 1 < DIM) outp[(size_t)r0 * DIM + col + 1] = acc[nt][1];
            outp[(size_t)(r0 + 8) * DIM + col] = acc[nt][2];
            if (col + 1 < DIM) outp[(size_t)(r0 + 8) * DIM + col + 1] = acc[nt][3];
        }
    }
}

// ---------------- reduce + L2 normalize (shfl-based) ----------------
__global__ __launch_bounds__(320) void reduce_norm_kernel(float* __restrict__ out)
{
    __shared__ float wsum[10];
    const int b = blockIdx.x;
    const int tid = threadIdx.x;

    float attr = 0.f;
    if (tid < DIM) {
#pragma unroll
        for (int s = 0; s < SPLITS; s++)
            attr += g_partial[((size_t)s * BATCH + b) * DIM + tid];
    }
    float sq = attr * attr;
#pragma unroll
    for (int off = 16; off > 0; off >>= 1)
        sq += __shfl_xor_sync(0xFFFFFFFFu, sq, off);
    if ((tid & 31) == 0) wsum[tid >> 5] = sq;
    __syncthreads();
    float total = 0.f;
#pragma unroll
    for (int w = 0; w < 10; w++) total += wsum[w];
    const float inv = 1.f / (sqrtf(total) + 1e-7f);
    if (tid < DIM) out[(size_t)b * DIM + tid] = attr * inv;
}

extern "C" void kernel_launch(void* const* d_in, const int* in_sizes, int n_in,
                              void* d_out, int out_size)
{
    const float* labels = (const float*)d_in[0];   // (1024, 50000)
    const float* weight = (const float*)d_in[1];   // (50000, 300)
    float* out = (float*)d_out;                    // (1024, 300)

    cudaFuncSetAttribute(gemm_kernel, cudaFuncAttributeMaxDynamicSharedMemorySize,
                         SMEM_TOTAL);

    prep_kernel<<<dim3(K_PAD / 64, BN_ALLOC / 32), 256>>>(weight);
    gemm_kernel<<<dim3(BATCH / BM, SPLITS), 256, SMEM_TOTAL>>>(labels);
    reduce_norm_kernel<<<BATCH, 320>>>(out);
}

// round 12
// speedup vs baseline: 1.1544x; 1.1544x over previous
#include <cuda_runtime.h>
#include <cuda_bf16.h>
#include <cstdint>

#define BATCH 1024
#define VOCAB 50000
#define DIM   300

#define BM      64
#define BN      304             // 38 n8-tiles, covers DIM=300
#define BN_ALLOC 320            // allocation/prep padding
#define KC      32
#define SPLITS  9
#define SEG     5568            // SPLITS*SEG = 50112 >= VOCAB, mult of KC
#define K_PAD   50112
#define NCHUNK  (SEG / KC)      // 174

// -------- static device scratch (no allocations allowed) --------
__device__ __nv_bfloat16 g_bhi[(size_t)BN_ALLOC * K_PAD];   // weight hi, [n][k]
__device__ __nv_bfloat16 g_blo[(size_t)BN_ALLOC * K_PAD];   // weight lo, [n][k]
__device__ float g_partial[(size_t)SPLITS * BATCH * DIM];

// smem layout. Row stride 40 bf16 = 80B (conflict-free frags).
#define A_STRIDE 80
#define A_BYTES  (64 * A_STRIDE)        // 5120
#define B_BYTES  (BN * A_STRIDE)        // 24320
#define BUF_BYTES (2 * A_BYTES + 2 * B_BYTES)   // 58880
#define A_HI(b) ((b) * BUF_BYTES + 0)
#define A_LO(b) ((b) * BUF_BYTES + A_BYTES)
#define B_HI(b) ((b) * BUF_BYTES + 2 * A_BYTES)
#define B_LO(b) ((b) * BUF_BYTES + 2 * A_BYTES + B_BYTES)
#define SMEM_TOTAL (2 * BUF_BYTES)      // 117760

__device__ __forceinline__ uint32_t smem_u32(const void* p) {
    uint32_t a;
    asm("{ .reg .u64 t; cvta.to.shared.u64 t, %1; cvt.u32.u64 %0, t; }"
        : "=r"(a) : "l"(p));
    return a;
}
__device__ __forceinline__ void cp_async16(uint32_t dst, const void* src) {
    asm volatile("{ .reg .u64 g; cvta.to.global.u64 g, %1; "
                 "cp.async.ca.shared.global [%0], [g], 16; }"
                 :: "r"(dst), "l"(src) : "memory");
}
#define CP_COMMIT() asm volatile("cp.async.commit_group;" ::: "memory")
#define CP_WAIT0()  asm volatile("cp.async.wait_group 0;" ::: "memory")

__device__ __forceinline__ void mma16816(float* d, const uint32_t* a,
                                         uint32_t b0, uint32_t b1) {
    asm volatile("mma.sync.aligned.m16n8k16.row.col.f32.bf16.bf16.f32 "
                 "{%0,%1,%2,%3}, {%4,%5,%6,%7}, {%8,%9}, {%0,%1,%2,%3};"
                 : "+f"(d[0]), "+f"(d[1]), "+f"(d[2]), "+f"(d[3])
                 : "r"(a[0]), "r"(a[1]), "r"(a[2]), "r"(a[3]), "r"(b0), "r"(b1));
}

// split (x,y) into packed bf16x2 hi + lo (low half = x)
__device__ __forceinline__ void cvt_split2(float x, float y, uint32_t& h, uint32_t& l) {
    uint32_t hh;
    asm("cvt.rn.bf16x2.f32 %0, %1, %2;" : "=r"(hh) : "f"(y), "f"(x));
    float hx = __uint_as_float(hh << 16);
    float hy = __uint_as_float(hh & 0xFFFF0000u);
    float lx = x - hx, ly = y - hy;
    asm("cvt.rn.bf16x2.f32 %0, %1, %2;" : "=r"(l) : "f"(ly), "f"(lx));
    h = hh;
}

// ---------------- prep: weight f32 [K][300] -> bf16 hi/lo [320][K_PAD] ----------------
// 64k x 64n tile per block; 16 loads/thread (deep MLP), 2x uint4 stores per array.
__global__ __launch_bounds__(256) void prep_kernel(const float* __restrict__ weight)
{
    __shared__ float t[64][65];
    const int k0 = blockIdx.x * 64;
    const int n0 = blockIdx.y * 64;
    const int tn = threadIdx.x & 63;          // n within tile
    const int tk = threadIdx.x >> 6;          // 0..3
#pragma unroll
    for (int i = 0; i < 16; i++) {
        const int k = k0 + tk + i * 4;
        const int n = n0 + tn;
        t[tk + i * 4][tn] = (k < VOCAB && n < DIM) ? weight[(size_t)k * DIM + n] : 0.f;
    }
    __syncthreads();
    const int nl = threadIdx.x >> 2;           // 0..63
    const int kg = (threadIdx.x & 3) * 16;     // 0..48 (16 consecutive k)
    __nv_bfloat16 harr[16], larr[16];
#pragma unroll
    for (int j = 0; j < 16; j++) {
        const float v = t[kg + j][nl];
        const __nv_bfloat16 h = __float2bfloat16_rn(v);
        harr[j] = h;
        larr[j] = __float2bfloat16_rn(v - __bfloat162float(h));
    }
    const size_t off = (size_t)(n0 + nl) * K_PAD + k0 + kg;
    *reinterpret_cast<uint4*>(g_bhi + off)     = *reinterpret_cast<uint4*>(harr);
    *reinterpret_cast<uint4*>(g_bhi + off + 8) = *reinterpret_cast<uint4*>(harr + 8);
    *reinterpret_cast<uint4*>(g_blo + off)     = *reinterpret_cast<uint4*>(larr);
    *reinterpret_cast<uint4*>(g_blo + off + 8) = *reinterpret_cast<uint4*>(larr + 8);
}

// ---------------- GEMM: HMMA bf16 3-term split, split-K (R9 proven design) -------------
__global__ __launch_bounds__(256, 1) void gemm_kernel(const float* __restrict__ labels)
{
    extern __shared__ char smem[];
    const uint32_t smem_base = smem_u32(smem);

    const int tid = threadIdx.x;
    const int wid = tid >> 5;
    const int lane = tid & 31;
    const int lr = lane >> 2;            // 0..7
    const int lc = lane & 3;             // 0..3
    const int m_strip = wid & 3;         // 4 m16 strips
    const int nt0 = (wid >> 2) * 19;     // n-tile base: 0 or 19

    const int row0 = blockIdx.x * BM;
    const int s = blockIdx.y;
    const int k_start = s * SEG;

    // A f32 staging indices
    const int arow = tid >> 3;           // 0..31 (rows r and r+32)
    const int af4 = tid & 7;             // float4 col 0..7

    float acc[19][4];
#pragma unroll
    for (int nt = 0; nt < 19; nt++)
#pragma unroll
        for (int i = 0; i < 4; i++) acc[nt][i] = 0.f;

    auto loadA = [&](int kc0, float4* v) {
#pragma unroll
        for (int i = 0; i < 2; i++) {
            const int r = row0 + arow + i * 32;
            const int k = kc0 + af4 * 4;
            const float* src = labels + (size_t)r * VOCAB + k;
            if (k + 3 < VOCAB) {
                v[i] = *reinterpret_cast<const float4*>(src);
            } else {
                v[i].x = (k     < VOCAB) ? src[0] : 0.f;
                v[i].y = (k + 1 < VOCAB) ? src[1] : 0.f;
                v[i].z = (k + 2 < VOCAB) ? src[2] : 0.f;
                v[i].w = (k + 3 < VOCAB) ? src[3] : 0.f;
            }
        }
    };
    auto stsA = [&](int buf, const float4* v) {
#pragma unroll
        for (int i = 0; i < 2; i++) {
            uint32_t h0, l0, h1, l1;
            cvt_split2(v[i].x, v[i].y, h0, l0);
            cvt_split2(v[i].z, v[i].w, h1, l1);
            const int off = (arow + i * 32) * A_STRIDE + af4 * 8;
            *reinterpret_cast<uint32_t*>(smem + A_HI(buf) + off)     = h0;
            *reinterpret_cast<uint32_t*>(smem + A_HI(buf) + off + 4) = h1;
            *reinterpret_cast<uint32_t*>(smem + A_LO(buf) + off)     = l0;
            *reinterpret_cast<uint32_t*>(smem + A_LO(buf) + off + 4) = l1;
        }
    };
    auto loadB = [&](int kc0, int buf) {
#pragma unroll
        for (int i = 0; i < 5; i++) {
            const int idx = tid + 256 * i;     // 0..1279, valid < 1216
            if (idx < BN * 4) {
                const int n = idx >> 2;
                const int seg = idx & 3;
                const int doff = n * A_STRIDE + seg * 16;
                const size_t goff = (size_t)n * K_PAD + kc0 + seg * 8;
                cp_async16(smem_base + B_HI(buf) + doff, g_bhi + goff);
                cp_async16(smem_base + B_LO(buf) + doff, g_blo + goff);
            }
        }
        CP_COMMIT();
    };
    auto compute = [&](int buf) {
        const int abase = A_HI(buf) + (m_strip * 16 + lr) * A_STRIDE + lc * 4;
        const int bbase = B_HI(buf) + (nt0 * 8 + lr) * A_STRIDE + lc * 4;
        // preload A fragments for this m-strip (hi+lo, both kk halves)
        uint32_t ah[2][4], al[2][4];
#pragma unroll
        for (int kk = 0; kk < 2; kk++) {
            const int a0 = abase + kk * 32;
            ah[kk][0] = *reinterpret_cast<const uint32_t*>(smem + a0);
            ah[kk][1] = *reinterpret_cast<const uint32_t*>(smem + a0 + 8 * A_STRIDE);
            ah[kk][2] = *reinterpret_cast<const uint32_t*>(smem + a0 + 16);
            ah[kk][3] = *reinterpret_cast<const uint32_t*>(smem + a0 + 8 * A_STRIDE + 16);
            const int a1 = a0 + A_BYTES;
            al[kk][0] = *reinterpret_cast<const uint32_t*>(smem + a1);
            al[kk][1] = *reinterpret_cast<const uint32_t*>(smem + a1 + 8 * A_STRIDE);
            al[kk][2] = *reinterpret_cast<const uint32_t*>(smem + a1 + 16);
            al[kk][3] = *reinterpret_cast<const uint32_t*>(smem + a1 + 8 * A_STRIDE + 16);
        }
        // term-outermost: 19 independent accumulators between reuses
#pragma unroll
        for (int t = 0; t < 3; t++) {
            const int bregion = (t == 1) ? B_BYTES : 0;   // t==1 -> B lo
#pragma unroll
            for (int kk = 0; kk < 2; kk++) {
                const uint32_t* af = (t == 2) ? al[kk] : ah[kk];
#pragma unroll
                for (int nt = 0; nt < 19; nt++) {
                    const int b0 = bbase + bregion + nt * 8 * A_STRIDE + kk * 32;
                    const uint32_t bb0 = *reinterpret_cast<const uint32_t*>(smem + b0);
                    const uint32_t bb1 = *reinterpret_cast<const uint32_t*>(smem + b0 + 16);
                    mma16816(acc[nt], af, bb0, bb1);
                }
            }
        }
    };

    // ---- prologue: stage chunk 0 ----
    {
        float4 v[2];
        loadB(k_start, 0);
        loadA(k_start, v);
        stsA(0, v);
        CP_WAIT0();
        __syncthreads();
    }

    // ---- main loop: issue loads early, hide LDG/cp.async under compute ----
    for (int c = 0; c < NCHUNK; c++) {
        const int buf = c & 1;
        const bool has_next = (c + 1 < NCHUNK);
        float4 v[2];
        if (has_next) {
            loadB(k_start + (c + 1) * KC, buf ^ 1);   // async into other buffer
            loadA(k_start + (c + 1) * KC, v);          // LDG in flight during compute
        }
        compute(buf);
        if (has_next) {
            stsA(buf ^ 1, v);                          // consume LDG after compute
            CP_WAIT0();
        }
        __syncthreads();
    }

    // ---- epilogue: write split-K partials ----
    float* outp = g_partial + (size_t)s * BATCH * DIM;
    const int r0 = row0 + m_strip * 16 + lr;
#pragma unroll
    for (int nt = 0; nt < 19; nt++) {
        const int col = (nt0 + nt) * 8 + 2 * lc;
        if (col < DIM) {
            outp[(size_t)r0 * DIM + col] = acc[nt][0];
            if (col + 1 < DIM) outp[(size_t)r0 * DIM + col + 1] = acc[nt][1];
            outp[(size_t)(r0 + 8) * DIM + col] = acc[nt][2];
            if (col + 1 < DIM) outp[(size_t)(r0 + 8) * DIM + col + 1] = acc[nt][3];
        }
    }
}

// ---------------- reduce + L2 normalize (shfl-based) ----------------
__global__ __launch_bounds__(320) void reduce_norm_kernel(float* __restrict__ out)
{
    __shared__ float wsum[10];
    const int b = blockIdx.x;
    const int tid = threadIdx.x;

    float attr = 0.f;
    if (tid < DIM) {
#pragma unroll
        for (int s = 0; s < SPLITS; s++)
            attr += g_partial[((size_t)s * BATCH + b) * DIM + tid];
    }
    float sq = attr * attr;
#pragma unroll
    for (int off = 16; off > 0; off >>= 1)
        sq += __shfl_xor_sync(0xFFFFFFFFu, sq, off);
    if ((tid & 31) == 0) wsum[tid >> 5] = sq;
    __syncthreads();
    float total = 0.f;
#pragma unroll
    for (int w = 0; w < 10; w++) total += wsum[w];
    const float inv = 1.f / (sqrtf(total) + 1e-7f);
    if (tid < DIM) out[(size_t)b * DIM + tid] = attr * inv;
}

extern "C" void kernel_launch(void* const* d_in, const int* in_sizes, int n_in,
                              void* d_out, int out_size)
{
    const float* labels = (const float*)d_in[0];   // (1024, 50000)
    const float* weight = (const float*)d_in[1];   // (50000, 300)
    float* out = (float*)d_out;                    // (1024, 300)

    cudaFuncSetAttribute(gemm_kernel, cudaFuncAttributeMaxDynamicSharedMemorySize,
                         SMEM_TOTAL);

    prep_kernel<<<dim3(K_PAD / 64, BN_ALLOC / 64), 256>>>(weight);
    gemm_kernel<<<dim3(BATCH / BM, SPLITS), 256, SMEM_TOTAL>>>(labels);
    reduce_norm_kernel<<<BATCH, 320>>>(out);
}